// round 2
// baseline (speedup 1.0000x reference)
#include <cuda_runtime.h>
#include <cuda_bf16.h>

// Problem dims
#define B_  2
#define S_  2048
#define D_  1024
#define H_  16
#define HD_ 64
#define GM  (B_ * S_)   // 4096
#define GN  D_          // 1024
#define GK  D_          // 1024

// Scratch (allocation-free rule: __device__ globals)
__device__ float g_q[B_ * H_ * S_ * HD_];    // [B,H,S,HD]
__device__ float g_k[B_ * H_ * S_ * HD_];
__device__ float g_v[B_ * H_ * S_ * HD_];
__device__ float g_ctx[B_ * S_ * D_];        // [B,S,D]

// ---------------------------------------------------------------------------
// 128x128x8 register-blocked fp32 GEMM: out = X @ W, written to [B,H,S,HD]
// grid: (GN/128, GM/128, 3), 256 threads
// ---------------------------------------------------------------------------
__global__ __launch_bounds__(256, 2)
void qkv_gemm_kernel(const float* __restrict__ X,
                     const float* __restrict__ Wq,
                     const float* __restrict__ Wk,
                     const float* __restrict__ Wv)
{
    const float* W   = (blockIdx.z == 0) ? Wq : (blockIdx.z == 1) ? Wk : Wv;
    float*       Out = (blockIdx.z == 0) ? g_q : (blockIdx.z == 1) ? g_k : g_v;

    __shared__ float As[8][128];
    __shared__ float Bs[8][128];

    const int m0 = blockIdx.y * 128;
    const int n0 = blockIdx.x * 128;
    const int t  = threadIdx.x;
    const int tm = t >> 4;          // 0..15 -> rows tm*8..tm*8+7
    const int tn = t & 15;          // 0..15 -> cols tn*8..tn*8+7

    const int arow = t >> 1, acol = (t & 1) * 4;   // A tile load: 1 float4/thread
    const int brow = t >> 5, bcol = (t & 31) * 4;  // B tile load: 1 float4/thread

    float acc[8][8] = {};

    for (int k0 = 0; k0 < GK; k0 += 8) {
        float4 av = *(const float4*)&X[(size_t)(m0 + arow) * GK + k0 + acol];
        float4 bv = *(const float4*)&W[(size_t)(k0 + brow) * GN + n0 + bcol];
        __syncthreads();
        As[acol + 0][arow] = av.x;
        As[acol + 1][arow] = av.y;
        As[acol + 2][arow] = av.z;
        As[acol + 3][arow] = av.w;
        *(float4*)&Bs[brow][bcol] = bv;
        __syncthreads();
        #pragma unroll
        for (int k = 0; k < 8; k++) {
            float a[8], b[8];
            #pragma unroll
            for (int i = 0; i < 8; i++) a[i] = As[k][tm * 8 + i];
            #pragma unroll
            for (int j = 0; j < 8; j++) b[j] = Bs[k][tn * 8 + j];
            #pragma unroll
            for (int i = 0; i < 8; i++)
                #pragma unroll
                for (int j = 0; j < 8; j++)
                    acc[i][j] += a[i] * b[j];
        }
    }

    // Write to [B, H, S, HD]
    #pragma unroll
    for (int i = 0; i < 8; i++) {
        int m = m0 + tm * 8 + i;
        int b = m >> 11;            // m / S_
        int s = m & (S_ - 1);
        #pragma unroll
        for (int j = 0; j < 8; j++) {
            int n  = n0 + tn * 8 + j;
            int h  = n >> 6;
            int hd = n & 63;
            Out[((size_t)((b * H_ + h) * S_) + s) * HD_ + hd] = acc[i][j];
        }
    }
}

// ---------------------------------------------------------------------------
// Output projection: d_out = ctx @ Wo + bo   (standard [4096,1024] layout)
// ---------------------------------------------------------------------------
__global__ __launch_bounds__(256, 2)
void out_gemm_kernel(const float* __restrict__ Wo,
                     const float* __restrict__ bo,
                     float* __restrict__ Out)
{
    const float* X = g_ctx;

    __shared__ float As[8][128];
    __shared__ float Bs[8][128];

    const int m0 = blockIdx.y * 128;
    const int n0 = blockIdx.x * 128;
    const int t  = threadIdx.x;
    const int tm = t >> 4;
    const int tn = t & 15;

    const int arow = t >> 1, acol = (t & 1) * 4;
    const int brow = t >> 5, bcol = (t & 31) * 4;

    float acc[8][8] = {};

    for (int k0 = 0; k0 < GK; k0 += 8) {
        float4 av = *(const float4*)&X[(size_t)(m0 + arow) * GK + k0 + acol];
        float4 bv = *(const float4*)&Wo[(size_t)(k0 + brow) * GN + n0 + bcol];
        __syncthreads();
        As[acol + 0][arow] = av.x;
        As[acol + 1][arow] = av.y;
        As[acol + 2][arow] = av.z;
        As[acol + 3][arow] = av.w;
        *(float4*)&Bs[brow][bcol] = bv;
        __syncthreads();
        #pragma unroll
        for (int k = 0; k < 8; k++) {
            float a[8], b[8];
            #pragma unroll
            for (int i = 0; i < 8; i++) a[i] = As[k][tm * 8 + i];
            #pragma unroll
            for (int j = 0; j < 8; j++) b[j] = Bs[k][tn * 8 + j];
            #pragma unroll
            for (int i = 0; i < 8; i++)
                #pragma unroll
                for (int j = 0; j < 8; j++)
                    acc[i][j] += a[i] * b[j];
        }
    }

    #pragma unroll
    for (int i = 0; i < 8; i++) {
        int m = m0 + tm * 8 + i;
        #pragma unroll
        for (int j = 0; j < 8; j++) {
            int n = n0 + tn * 8 + j;
            Out[(size_t)m * GN + n] = acc[i][j] + bo[n];
        }
    }
}

// ---------------------------------------------------------------------------
// Flash attention (fp32, causal). grid: (S/64, B*H), 256 threads.
// Dynamic smem: Qs/Ks/Vs/Ss, each 64 x 68 floats.
// Thread (ty,tx) in 16x16: owns rows ty*4+{0..3}, cols tx*4+{0..3}.
// ---------------------------------------------------------------------------
#define APITCH 68
#define SMEM_ATTN (4 * 64 * APITCH * 4)

__global__ __launch_bounds__(256, 3)
void attn_kernel()
{
    extern __shared__ float sm[];
    float* Qs = sm;
    float* Ks = Qs + 64 * APITCH;
    float* Vs = Ks + 64 * APITCH;
    float* Ss = Vs + 64 * APITCH;

    const int qb = blockIdx.x;        // query block (0..31)
    const int bh = blockIdx.y;        // fused b*H + h (0..31)
    const int t  = threadIdx.x;
    const int ty = t >> 4;            // 0..15
    const int tx = t & 15;            // 0..15

    const float* Qg = g_q + (size_t)bh * S_ * HD_;
    const float* Kg = g_k + (size_t)bh * S_ * HD_;
    const float* Vg = g_v + (size_t)bh * S_ * HD_;

    // Load Q tile: 64x64 floats = 1024 float4, 4 per thread
    for (int v = t; v < 1024; v += 256) {
        int row = v >> 4;
        int c4  = (v & 15) * 4;
        *(float4*)&Qs[row * APITCH + c4] =
            *(const float4*)&Qg[(size_t)(qb * 64 + row) * HD_ + c4];
    }

    float m_i[4], l_i[4];
    float acc[4][4] = {};
    #pragma unroll
    for (int i = 0; i < 4; i++) { m_i[i] = -1e30f; l_i[i] = 0.0f; }

    const float scale = 0.125f;  // 1/sqrt(64)

    for (int kb = 0; kb <= qb; kb++) {
        // Load K,V tiles
        for (int v = t; v < 1024; v += 256) {
            int row = v >> 4;
            int c4  = (v & 15) * 4;
            *(float4*)&Ks[row * APITCH + c4] =
                *(const float4*)&Kg[(size_t)(kb * 64 + row) * HD_ + c4];
            *(float4*)&Vs[row * APITCH + c4] =
                *(const float4*)&Vg[(size_t)(kb * 64 + row) * HD_ + c4];
        }
        __syncthreads();

        // S = Q K^T for the 4x4 micro tile
        float s[4][4] = {};
        #pragma unroll 4
        for (int kk = 0; kk < 64; kk += 4) {
            float4 qv[4], kv[4];
            #pragma unroll
            for (int i = 0; i < 4; i++)
                qv[i] = *(const float4*)&Qs[(ty * 4 + i) * APITCH + kk];
            #pragma unroll
            for (int j = 0; j < 4; j++)
                kv[j] = *(const float4*)&Ks[(tx * 4 + j) * APITCH + kk];
            #pragma unroll
            for (int i = 0; i < 4; i++)
                #pragma unroll
                for (int j = 0; j < 4; j++)
                    s[i][j] += qv[i].x * kv[j].x + qv[i].y * kv[j].y +
                               qv[i].z * kv[j].z + qv[i].w * kv[j].w;
        }

        // scale + causal mask
        #pragma unroll
        for (int i = 0; i < 4; i++) {
            int qg = qb * 64 + ty * 4 + i;
            #pragma unroll
            for (int j = 0; j < 4; j++) {
                int kg = kb * 64 + tx * 4 + j;
                s[i][j] = (kg > qg) ? -1e30f : s[i][j] * scale;
            }
        }

        // online softmax: row reductions over the 16 tx lanes
        #pragma unroll
        for (int i = 0; i < 4; i++) {
            float rmax = s[i][0];
            #pragma unroll
            for (int j = 1; j < 4; j++) rmax = fmaxf(rmax, s[i][j]);
            #pragma unroll
            for (int off = 8; off > 0; off >>= 1)
                rmax = fmaxf(rmax, __shfl_xor_sync(0xffffffffu, rmax, off));

            float m_new = fmaxf(m_i[i], rmax);
            float corr  = __expf(m_i[i] - m_new);

            float rsum = 0.0f;
            #pragma unroll
            for (int j = 0; j < 4; j++) {
                float p = __expf(s[i][j] - m_new);
                s[i][j] = p;
                rsum += p;
            }
            #pragma unroll
            for (int off = 8; off > 0; off >>= 1)
                rsum += __shfl_xor_sync(0xffffffffu, rsum, off);

            l_i[i] = l_i[i] * corr + rsum;
            m_i[i] = m_new;
            #pragma unroll
            for (int j = 0; j < 4; j++) acc[i][j] *= corr;
        }

        // write P to shared
        #pragma unroll
        for (int i = 0; i < 4; i++)
            #pragma unroll
            for (int j = 0; j < 4; j++)
                Ss[(ty * 4 + i) * APITCH + tx * 4 + j] = s[i][j];
        __syncthreads();

        // acc += P @ V
        #pragma unroll 4
        for (int kk = 0; kk < 64; kk += 4) {
            float4 pv[4];
            float  vvf[4][4];
            #pragma unroll
            for (int i = 0; i < 4; i++)
                pv[i] = *(const float4*)&Ss[(ty * 4 + i) * APITCH + kk];
            #pragma unroll
            for (int c = 0; c < 4; c++) {
                float4 tmp = *(const float4*)&Vs[(kk + c) * APITCH + tx * 4];
                vvf[c][0] = tmp.x; vvf[c][1] = tmp.y;
                vvf[c][2] = tmp.z; vvf[c][3] = tmp.w;
            }
            #pragma unroll
            for (int i = 0; i < 4; i++) {
                #pragma unroll
                for (int j = 0; j < 4; j++) {
                    acc[i][j] += pv[i].x * vvf[0][j] + pv[i].y * vvf[1][j] +
                                 pv[i].z * vvf[2][j] + pv[i].w * vvf[3][j];
                }
            }
        }
        __syncthreads();
    }

    // finalize: ctx[b, qg, h*64 + d] = acc / l
    const int b = bh >> 4;
    const int h = bh & 15;
    #pragma unroll
    for (int i = 0; i < 4; i++) {
        int   qg    = qb * 64 + ty * 4 + i;
        float inv_l = 1.0f / l_i[i];
        #pragma unroll
        for (int j = 0; j < 4; j++) {
            int d = tx * 4 + j;
            g_ctx[((size_t)(b * S_ + qg)) * D_ + h * HD_ + d] = acc[i][j] * inv_l;
        }
    }
}

// ---------------------------------------------------------------------------
extern "C" void kernel_launch(void* const* d_in, const int* in_sizes, int n_in,
                              void* d_out, int out_size)
{
    const float* x  = (const float*)d_in[0];
    const float* Wq = (const float*)d_in[1];
    const float* Wk = (const float*)d_in[2];
    const float* Wv = (const float*)d_in[3];
    const float* Wo = (const float*)d_in[4];
    const float* bo = (const float*)d_in[5];
    float*       out = (float*)d_out;

    cudaFuncSetAttribute(attn_kernel,
                         cudaFuncAttributeMaxDynamicSharedMemorySize, SMEM_ATTN);

    dim3 gqkv(GN / 128, GM / 128, 3);
    qkv_gemm_kernel<<<gqkv, 256>>>(x, Wq, Wk, Wv);

    dim3 gattn(S_ / 64, B_ * H_);
    attn_kernel<<<gattn, 256, SMEM_ATTN>>>();

    dim3 gout(GN / 128, GM / 128);
    out_gemm_kernel<<<gout, 256>>>(Wo, bo, out);
}

// round 5
// speedup vs baseline: 4.9942x; 4.9942x over previous
#include <cuda_runtime.h>
#include <cuda_bf16.h>
#include <cstdint>

// Problem dims
#define B_  2
#define S_  2048
#define D_  1024
#define H_  16
#define HD_ 64
#define GM  (B_ * S_)   // 4096
#define GN  D_          // 1024
#define GK  D_          // 1024

// ---------------------------------------------------------------------------
// Scratch (__device__ globals; allocation-free rule)
// ---------------------------------------------------------------------------
__device__ __nv_bfloat16 g_x_hi[GM * GK];
__device__ __nv_bfloat16 g_x_lo[GM * GK];
__device__ __nv_bfloat16 g_qh[B_ * H_ * S_ * HD_];   // [B,H,S,HD]
__device__ __nv_bfloat16 g_ql[B_ * H_ * S_ * HD_];
__device__ __nv_bfloat16 g_kh[B_ * H_ * S_ * HD_];
__device__ __nv_bfloat16 g_kl[B_ * H_ * S_ * HD_];
__device__ __nv_bfloat16 g_vh[B_ * H_ * S_ * HD_];
__device__ __nv_bfloat16 g_vl[B_ * H_ * S_ * HD_];
__device__ __nv_bfloat16 g_ctx_hi[GM * GK];          // [B,S,D]
__device__ __nv_bfloat16 g_ctx_lo[GM * GK];
// transposed weights [N, K] K-major
__device__ __nv_bfloat16 g_wqt_hi[GN * GK];
__device__ __nv_bfloat16 g_wqt_lo[GN * GK];
__device__ __nv_bfloat16 g_wkt_hi[GN * GK];
__device__ __nv_bfloat16 g_wkt_lo[GN * GK];
__device__ __nv_bfloat16 g_wvt_hi[GN * GK];
__device__ __nv_bfloat16 g_wvt_lo[GN * GK];
__device__ __nv_bfloat16 g_wot_hi[GN * GK];
__device__ __nv_bfloat16 g_wot_lo[GN * GK];

// ---------------------------------------------------------------------------
// Warp-MMA primitives (sm_80+ instructions; valid for plain sm_103 PTX target)
// ---------------------------------------------------------------------------
__device__ __forceinline__ uint32_t smem_u32(const void* p) {
    uint32_t a;
    asm("{ .reg .u64 t; cvta.to.shared.u64 t, %1; cvt.u32.u64 %0, t; }"
        : "=r"(a) : "l"(p));
    return a;
}

__device__ __forceinline__ void mma16816(float* c, const uint32_t* a,
                                         uint32_t b0, uint32_t b1) {
    asm volatile(
        "mma.sync.aligned.m16n8k16.row.col.f32.bf16.bf16.f32 "
        "{%0,%1,%2,%3}, {%4,%5,%6,%7}, {%8,%9}, {%0,%1,%2,%3};"
        : "+f"(c[0]), "+f"(c[1]), "+f"(c[2]), "+f"(c[3])
        : "r"(a[0]), "r"(a[1]), "r"(a[2]), "r"(a[3]), "r"(b0), "r"(b1));
}

__device__ __forceinline__ void ldmx4(uint32_t* r, uint32_t addr) {
    asm volatile("ldmatrix.sync.aligned.m8n8.x4.shared.b16 {%0,%1,%2,%3}, [%4];"
        : "=r"(r[0]), "=r"(r[1]), "=r"(r[2]), "=r"(r[3]) : "r"(addr));
}

__device__ __forceinline__ void ldmx4t(uint32_t* r, uint32_t addr) {
    asm volatile("ldmatrix.sync.aligned.m8n8.x4.trans.shared.b16 {%0,%1,%2,%3}, [%4];"
        : "=r"(r[0]), "=r"(r[1]), "=r"(r[2]), "=r"(r[3]) : "r"(addr));
}

__device__ __forceinline__ unsigned pack_hi(float x, float y) {
    __nv_bfloat162 t = __floats2bfloat162_rn(x, y);
    return *reinterpret_cast<unsigned*>(&t);
}
__device__ __forceinline__ unsigned pack_lo(float x, float y) {
    float xr = x - __bfloat162float(__float2bfloat16(x));
    float yr = y - __bfloat162float(__float2bfloat16(y));
    __nv_bfloat162 t = __floats2bfloat162_rn(xr, yr);
    return *reinterpret_cast<unsigned*>(&t);
}

// ---------------------------------------------------------------------------
// GEMM: C[128,128] tile of A[M,K] @ B[N,K]^T, split-bf16 3-term, fp32 acc.
// 256 threads = 8 warps (2m x 4n); warp tile 64x32; KC=32.
// MODE 0: A = x, B = Wq/Wk/Wv (blockIdx.z); out -> bf16 hi/lo [B,H,S,HD]
// MODE 1: A = ctx, B = Wo; out -> fp32 [M,N] + bias
// ---------------------------------------------------------------------------
#define GP 40            // smem pitch in bf16 elements (80 bytes)

template <int MODE>
__global__ __launch_bounds__(256, 1)
void mma_gemm_kernel(const float* __restrict__ bias, float* __restrict__ dout)
{
    __shared__ __nv_bfloat16 sAh[128 * GP];
    __shared__ __nv_bfloat16 sAl[128 * GP];
    __shared__ __nv_bfloat16 sBh[128 * GP];
    __shared__ __nv_bfloat16 sBl[128 * GP];

    const __nv_bfloat16 *Ah, *Al, *Bh, *Bl;
    __nv_bfloat16 *OutH = nullptr, *OutL = nullptr;
    if (MODE == 0) {
        Ah = g_x_hi; Al = g_x_lo;
        if (blockIdx.z == 0)      { Bh = g_wqt_hi; Bl = g_wqt_lo; OutH = g_qh; OutL = g_ql; }
        else if (blockIdx.z == 1) { Bh = g_wkt_hi; Bl = g_wkt_lo; OutH = g_kh; OutL = g_kl; }
        else                      { Bh = g_wvt_hi; Bl = g_wvt_lo; OutH = g_vh; OutL = g_vl; }
    } else {
        Ah = g_ctx_hi; Al = g_ctx_lo; Bh = g_wot_hi; Bl = g_wot_lo;
    }

    const int m0   = blockIdx.y * 128;
    const int n0   = blockIdx.x * 128;
    const int t    = threadIdx.x;
    const int lane = t & 31;
    const int wid  = t >> 5;
    const int wm   = wid >> 2;     // 0..1
    const int wn   = wid & 3;      // 0..3

    const uint32_t uAh = smem_u32(sAh), uAl = smem_u32(sAl);
    const uint32_t uBh = smem_u32(sBh), uBl = smem_u32(sBl);

    // gmem load mapping: thread t loads 32B (2 x uint4) per tile
    const int lrow = t >> 1;
    const int lq   = (t & 1) * 2;  // quad index 0 or 2

    float acc[4][4][4] = {};

    for (int c = 0; c < GK / 32; c++) {
        __syncthreads();
        {
            size_t goff = (size_t)lrow * (GK * 2) + (size_t)c * 64 + lq * 16;
            const uint4* pa_h = (const uint4*)((const char*)Ah + (size_t)m0 * (GK * 2) + goff);
            const uint4* pa_l = (const uint4*)((const char*)Al + (size_t)m0 * (GK * 2) + goff);
            const uint4* pb_h = (const uint4*)((const char*)Bh + (size_t)n0 * (GK * 2) + goff);
            const uint4* pb_l = (const uint4*)((const char*)Bl + (size_t)n0 * (GK * 2) + goff);
            int soff = lrow * (GP * 2) + lq * 16;
            *(uint4*)((char*)sAh + soff)      = pa_h[0];
            *(uint4*)((char*)sAh + soff + 16) = pa_h[1];
            *(uint4*)((char*)sAl + soff)      = pa_l[0];
            *(uint4*)((char*)sAl + soff + 16) = pa_l[1];
            *(uint4*)((char*)sBh + soff)      = pb_h[0];
            *(uint4*)((char*)sBh + soff + 16) = pb_h[1];
            *(uint4*)((char*)sBl + soff)      = pb_l[0];
            *(uint4*)((char*)sBl + soff + 16) = pb_l[1];
        }
        __syncthreads();

        #pragma unroll
        for (int ks = 0; ks < 2; ks++) {
            uint32_t a_h[4][4], a_l[4][4];
            int abyte = (wm * 64 + (lane & 15)) * (GP * 2) + ks * 32 + (lane >> 4) * 16;
            #pragma unroll
            for (int mt = 0; mt < 4; mt++) {
                ldmx4(a_h[mt], uAh + abyte + mt * 16 * (GP * 2));
                ldmx4(a_l[mt], uAl + abyte + mt * 16 * (GP * 2));
            }
            #pragma unroll
            for (int j = 0; j < 2; j++) {
                uint32_t b_h[4], b_l[4];
                int bbyte = (wn * 32 + j * 16 + ((lane >> 4) << 3) + (lane & 7)) * (GP * 2)
                          + ks * 32 + ((lane >> 3) & 1) * 16;
                ldmx4(b_h, uBh + bbyte);
                ldmx4(b_l, uBl + bbyte);
                #pragma unroll
                for (int mt = 0; mt < 4; mt++) {
                    mma16816(acc[mt][2 * j],     a_h[mt], b_h[0], b_h[1]);
                    mma16816(acc[mt][2 * j],     a_h[mt], b_l[0], b_l[1]);
                    mma16816(acc[mt][2 * j],     a_l[mt], b_h[0], b_h[1]);
                    mma16816(acc[mt][2 * j + 1], a_h[mt], b_h[2], b_h[3]);
                    mma16816(acc[mt][2 * j + 1], a_h[mt], b_l[2], b_l[3]);
                    mma16816(acc[mt][2 * j + 1], a_l[mt], b_h[2], b_h[3]);
                }
            }
        }
    }

    // Epilogue
    #pragma unroll
    for (int mt = 0; mt < 4; mt++) {
        int mA = m0 + wm * 64 + mt * 16 + (lane >> 2);
        int mB = mA + 8;
        #pragma unroll
        for (int nt = 0; nt < 4; nt++) {
            int n = n0 + wn * 32 + nt * 8 + (lane & 3) * 2;
            float c0 = acc[mt][nt][0], c1 = acc[mt][nt][1];
            float c2 = acc[mt][nt][2], c3 = acc[mt][nt][3];
            if (MODE == 0) {
                int h = n >> 6, hd = n & 63;
                {
                    int b = mA >> 11, s = mA & (S_ - 1);
                    size_t o = ((size_t)((b * H_ + h) * S_) + s) * HD_ + hd;
                    *(unsigned*)&OutH[o] = pack_hi(c0, c1);
                    *(unsigned*)&OutL[o] = pack_lo(c0, c1);
                }
                {
                    int b = mB >> 11, s = mB & (S_ - 1);
                    size_t o = ((size_t)((b * H_ + h) * S_) + s) * HD_ + hd;
                    *(unsigned*)&OutH[o] = pack_hi(c2, c3);
                    *(unsigned*)&OutL[o] = pack_lo(c2, c3);
                }
            } else {
                float b0 = bias[n], b1 = bias[n + 1];
                *(float2*)&dout[(size_t)mA * GN + n] = make_float2(c0 + b0, c1 + b1);
                *(float2*)&dout[(size_t)mB * GN + n] = make_float2(c2 + b0, c3 + b1);
            }
        }
    }
}

// ---------------------------------------------------------------------------
// Flash attention with warp MMA, causal, split-bf16 3-term.
// grid (S/64, B*H), 128 threads = 4 warps; warp owns 16 query rows.
// ---------------------------------------------------------------------------
#define AP 72     // smem pitch in bf16 (144 bytes)

__global__ __launch_bounds__(128, 3)
void attn_mma_kernel()
{
    __shared__ __nv_bfloat16 sKh[64 * AP];
    __shared__ __nv_bfloat16 sKl[64 * AP];
    __shared__ __nv_bfloat16 sVh[64 * AP];
    __shared__ __nv_bfloat16 sVl[64 * AP];

    const int qb   = blockIdx.x;
    const int bh   = blockIdx.y;
    const int t    = threadIdx.x;
    const int lane = t & 31;
    const int wid  = t >> 5;

    const size_t head_off = (size_t)bh * S_ * HD_;
    const __nv_bfloat16* Qh = g_qh + head_off + (size_t)qb * 64 * HD_;
    const __nv_bfloat16* Ql = g_ql + head_off + (size_t)qb * 64 * HD_;
    const __nv_bfloat16* Kh = g_kh + head_off;
    const __nv_bfloat16* Kl = g_kl + head_off;
    const __nv_bfloat16* Vh = g_vh + head_off;
    const __nv_bfloat16* Vl = g_vl + head_off;

    const uint32_t uKh = smem_u32(sKh), uKl = smem_u32(sKl);
    const uint32_t uVh = smem_u32(sVh), uVl = smem_u32(sVl);

    // ---- stage Q tile into sKh/sKl, extract A-fragments into registers ----
    #pragma unroll
    for (int p = 0; p < 4; p++) {
        int idx = t + p * 128;          // 0..511
        int row = idx >> 3, q = idx & 7;
        *(uint4*)((char*)sKh + row * (AP * 2) + q * 16) = ((const uint4*)Qh)[idx];
        *(uint4*)((char*)sKl + row * (AP * 2) + q * 16) = ((const uint4*)Ql)[idx];
    }
    __syncthreads();

    uint32_t aq_h[4][4], aq_l[4][4];
    {
        int qbyte = (wid * 16 + (lane & 15)) * (AP * 2) + (lane >> 4) * 16;
        #pragma unroll
        for (int kc = 0; kc < 4; kc++) {
            ldmx4(aq_h[kc], uKh + qbyte + kc * 32);
            ldmx4(aq_l[kc], uKl + qbyte + kc * 32);
        }
    }
    __syncthreads();

    float oAcc[8][4] = {};
    float m0r = -1e30f, m1r = -1e30f;
    float l0 = 0.0f, l1 = 0.0f;

    for (int kb = 0; kb <= qb; kb++) {
        // ---- load K/V hi+lo tiles (8KB each, contiguous in gmem) ----
        const uint4* gkh = (const uint4*)(Kh + (size_t)kb * 64 * HD_);
        const uint4* gkl = (const uint4*)(Kl + (size_t)kb * 64 * HD_);
        const uint4* gvh = (const uint4*)(Vh + (size_t)kb * 64 * HD_);
        const uint4* gvl = (const uint4*)(Vl + (size_t)kb * 64 * HD_);
        #pragma unroll
        for (int p = 0; p < 4; p++) {
            int idx = t + p * 128;
            int row = idx >> 3, q = idx & 7;
            int soff = row * (AP * 2) + q * 16;
            *(uint4*)((char*)sKh + soff) = gkh[idx];
            *(uint4*)((char*)sKl + soff) = gkl[idx];
            *(uint4*)((char*)sVh + soff) = gvh[idx];
            *(uint4*)((char*)sVl + soff) = gvl[idx];
        }
        __syncthreads();

        // ---- S = Q K^T (3-term) ----
        float sc[8][4] = {};
        #pragma unroll
        for (int kc = 0; kc < 4; kc++) {
            #pragma unroll
            for (int j = 0; j < 4; j++) {
                uint32_t b_h[4], b_l[4];
                int bbyte = (j * 16 + ((lane >> 4) << 3) + (lane & 7)) * (AP * 2)
                          + kc * 32 + ((lane >> 3) & 1) * 16;
                ldmx4(b_h, uKh + bbyte);
                ldmx4(b_l, uKl + bbyte);
                mma16816(sc[2 * j],     aq_h[kc], b_h[0], b_h[1]);
                mma16816(sc[2 * j],     aq_h[kc], b_l[0], b_l[1]);
                mma16816(sc[2 * j],     aq_l[kc], b_h[0], b_h[1]);
                mma16816(sc[2 * j + 1], aq_h[kc], b_h[2], b_h[3]);
                mma16816(sc[2 * j + 1], aq_h[kc], b_l[2], b_l[3]);
                mma16816(sc[2 * j + 1], aq_l[kc], b_h[2], b_h[3]);
            }
        }

        // ---- scale + causal mask (only diagonal block needs masking) ----
        #pragma unroll
        for (int nt = 0; nt < 8; nt++) {
            #pragma unroll
            for (int i = 0; i < 4; i++) sc[nt][i] *= 0.125f;
        }
        if (kb == qb) {
            int r0l = wid * 16 + (lane >> 2);
            #pragma unroll
            for (int nt = 0; nt < 8; nt++) {
                int col = nt * 8 + (lane & 3) * 2;
                if (col > r0l)         sc[nt][0] = -1e30f;
                if (col + 1 > r0l)     sc[nt][1] = -1e30f;
                if (col > r0l + 8)     sc[nt][2] = -1e30f;
                if (col + 1 > r0l + 8) sc[nt][3] = -1e30f;
            }
        }

        // ---- online softmax (rows r0 = regs 0,1; r1 = regs 2,3) ----
        float mx0 = -1e30f, mx1 = -1e30f;
        #pragma unroll
        for (int nt = 0; nt < 8; nt++) {
            mx0 = fmaxf(mx0, fmaxf(sc[nt][0], sc[nt][1]));
            mx1 = fmaxf(mx1, fmaxf(sc[nt][2], sc[nt][3]));
        }
        mx0 = fmaxf(mx0, __shfl_xor_sync(0xffffffffu, mx0, 1));
        mx0 = fmaxf(mx0, __shfl_xor_sync(0xffffffffu, mx0, 2));
        mx1 = fmaxf(mx1, __shfl_xor_sync(0xffffffffu, mx1, 1));
        mx1 = fmaxf(mx1, __shfl_xor_sync(0xffffffffu, mx1, 2));

        float mn0 = fmaxf(m0r, mx0), mn1 = fmaxf(m1r, mx1);
        float cr0 = __expf(m0r - mn0), cr1 = __expf(m1r - mn1);

        float sum0 = 0.0f, sum1 = 0.0f;
        #pragma unroll
        for (int nt = 0; nt < 8; nt++) {
            float p0 = __expf(sc[nt][0] - mn0);
            float p1 = __expf(sc[nt][1] - mn0);
            float p2 = __expf(sc[nt][2] - mn1);
            float p3 = __expf(sc[nt][3] - mn1);
            sc[nt][0] = p0; sc[nt][1] = p1; sc[nt][2] = p2; sc[nt][3] = p3;
            sum0 += p0 + p1;
            sum1 += p2 + p3;
        }
        sum0 += __shfl_xor_sync(0xffffffffu, sum0, 1);
        sum0 += __shfl_xor_sync(0xffffffffu, sum0, 2);
        sum1 += __shfl_xor_sync(0xffffffffu, sum1, 1);
        sum1 += __shfl_xor_sync(0xffffffffu, sum1, 2);

        l0 = l0 * cr0 + sum0;  m0r = mn0;
        l1 = l1 * cr1 + sum1;  m1r = mn1;

        #pragma unroll
        for (int nt = 0; nt < 8; nt++) {
            oAcc[nt][0] *= cr0; oAcc[nt][1] *= cr0;
            oAcc[nt][2] *= cr1; oAcc[nt][3] *= cr1;
        }

        // ---- O += P V (3-term; V B-frags via ldmatrix.trans) ----
        #pragma unroll
        for (int kc = 0; kc < 4; kc++) {
            uint32_t pa_h[4], pa_l[4];
            pa_h[0] = pack_hi(sc[2 * kc][0],     sc[2 * kc][1]);
            pa_h[1] = pack_hi(sc[2 * kc][2],     sc[2 * kc][3]);
            pa_h[2] = pack_hi(sc[2 * kc + 1][0], sc[2 * kc + 1][1]);
            pa_h[3] = pack_hi(sc[2 * kc + 1][2], sc[2 * kc + 1][3]);
            pa_l[0] = pack_lo(sc[2 * kc][0],     sc[2 * kc][1]);
            pa_l[1] = pack_lo(sc[2 * kc][2],     sc[2 * kc][3]);
            pa_l[2] = pack_lo(sc[2 * kc + 1][0], sc[2 * kc + 1][1]);
            pa_l[3] = pack_lo(sc[2 * kc + 1][2], sc[2 * kc + 1][3]);
            #pragma unroll
            for (int j = 0; j < 4; j++) {
                uint32_t v_h[4], v_l[4];
                int key  = kc * 16 + ((lane >> 3) & 1) * 8 + (lane & 7);
                int hd   = j * 16 + (lane >> 4) * 8;
                int vbyte = key * (AP * 2) + hd * 2;
                ldmx4t(v_h, uVh + vbyte);
                ldmx4t(v_l, uVl + vbyte);
                mma16816(oAcc[2 * j],     pa_h, v_h[0], v_h[1]);
                mma16816(oAcc[2 * j],     pa_h, v_l[0], v_l[1]);
                mma16816(oAcc[2 * j],     pa_l, v_h[0], v_h[1]);
                mma16816(oAcc[2 * j + 1], pa_h, v_h[2], v_h[3]);
                mma16816(oAcc[2 * j + 1], pa_h, v_l[2], v_l[3]);
                mma16816(oAcc[2 * j + 1], pa_l, v_h[2], v_h[3]);
            }
        }
        __syncthreads();
    }

    // ---- finalize: ctx hi/lo bf16 [B,S,D] ----
    const float inv0 = 1.0f / l0, inv1 = 1.0f / l1;
    const int b = bh >> 4, h = bh & 15;
    const int r0 = qb * 64 + wid * 16 + (lane >> 2);
    const int r1 = r0 + 8;
    #pragma unroll
    for (int nt = 0; nt < 8; nt++) {
        int hd = nt * 8 + (lane & 3) * 2;
        float v0 = oAcc[nt][0] * inv0, v1 = oAcc[nt][1] * inv0;
        float v2 = oAcc[nt][2] * inv1, v3 = oAcc[nt][3] * inv1;
        size_t o0 = ((size_t)(b * S_ + r0)) * D_ + h * HD_ + hd;
        size_t o1 = ((size_t)(b * S_ + r1)) * D_ + h * HD_ + hd;
        *(unsigned*)&g_ctx_hi[o0] = pack_hi(v0, v1);
        *(unsigned*)&g_ctx_lo[o0] = pack_lo(v0, v1);
        *(unsigned*)&g_ctx_hi[o1] = pack_hi(v2, v3);
        *(unsigned*)&g_ctx_lo[o1] = pack_lo(v2, v3);
    }
}

// ---------------------------------------------------------------------------
// fp32 -> (bf16 hi, bf16 lo) split, vectorized
// ---------------------------------------------------------------------------
__global__ void split_convert_kernel(const float4* __restrict__ src,
                                     __nv_bfloat162* __restrict__ hi,
                                     __nv_bfloat162* __restrict__ lo, int n4)
{
    int i = blockIdx.x * blockDim.x + threadIdx.x;
    if (i >= n4) return;
    float4 v = src[i];
    __nv_bfloat16 hx = __float2bfloat16(v.x), hy = __float2bfloat16(v.y);
    __nv_bfloat16 hz = __float2bfloat16(v.z), hw = __float2bfloat16(v.w);
    __nv_bfloat16 lx = __float2bfloat16(v.x - __bfloat162float(hx));
    __nv_bfloat16 ly = __float2bfloat16(v.y - __bfloat162float(hy));
    __nv_bfloat16 lz = __float2bfloat16(v.z - __bfloat162float(hz));
    __nv_bfloat16 lw = __float2bfloat16(v.w - __bfloat162float(hw));
    hi[i * 2]     = __nv_bfloat162(hx, hy);
    hi[i * 2 + 1] = __nv_bfloat162(hz, hw);
    lo[i * 2]     = __nv_bfloat162(lx, ly);
    lo[i * 2 + 1] = __nv_bfloat162(lz, lw);
}

// ---------------------------------------------------------------------------
// W [K,N] fp32 -> Wt [N,K] bf16 hi/lo  (32x32 smem tile transpose)
// ---------------------------------------------------------------------------
__global__ void transpose_split_kernel(const float* __restrict__ W,
                                       __nv_bfloat16* __restrict__ hi,
                                       __nv_bfloat16* __restrict__ lo)
{
    __shared__ float tile[32][33];
    const int tx = threadIdx.x, ty = threadIdx.y;
    const int k0 = blockIdx.y * 32;
    const int n0 = blockIdx.x * 32;
    #pragma unroll
    for (int j = 0; j < 4; j++)
        tile[ty + j * 8][tx] = W[(size_t)(k0 + ty + j * 8) * GN + n0 + tx];
    __syncthreads();
    #pragma unroll
    for (int j = 0; j < 4; j++) {
        int n = n0 + ty + j * 8;
        int k = k0 + tx;
        float v = tile[tx][ty + j * 8];
        __nv_bfloat16 hv = __float2bfloat16(v);
        hi[(size_t)n * GK + k] = hv;
        lo[(size_t)n * GK + k] = __float2bfloat16(v - __bfloat162float(hv));
    }
}

// ---------------------------------------------------------------------------
extern "C" void kernel_launch(void* const* d_in, const int* in_sizes, int n_in,
                              void* d_out, int out_size)
{
    const float* x  = (const float*)d_in[0];
    const float* Wq = (const float*)d_in[1];
    const float* Wk = (const float*)d_in[2];
    const float* Wv = (const float*)d_in[3];
    const float* Wo = (const float*)d_in[4];
    const float* bo = (const float*)d_in[5];
    float*       out = (float*)d_out;

    __nv_bfloat16 *xh, *xl;
    __nv_bfloat16 *wqh, *wql, *wkh, *wkl, *wvh, *wvl, *woh, *wol;
    cudaGetSymbolAddress((void**)&xh,  g_x_hi);
    cudaGetSymbolAddress((void**)&xl,  g_x_lo);
    cudaGetSymbolAddress((void**)&wqh, g_wqt_hi);
    cudaGetSymbolAddress((void**)&wql, g_wqt_lo);
    cudaGetSymbolAddress((void**)&wkh, g_wkt_hi);
    cudaGetSymbolAddress((void**)&wkl, g_wkt_lo);
    cudaGetSymbolAddress((void**)&wvh, g_wvt_hi);
    cudaGetSymbolAddress((void**)&wvl, g_wvt_lo);
    cudaGetSymbolAddress((void**)&woh, g_wot_hi);
    cudaGetSymbolAddress((void**)&wol, g_wot_lo);

    // 1) prep: split x, transpose+split all weights
    split_convert_kernel<<<(GM * GK / 4 + 255) / 256, 256>>>(
        (const float4*)x, (__nv_bfloat162*)xh, (__nv_bfloat162*)xl, GM * GK / 4);
    dim3 tgrid(GN / 32, GK / 32), tblk(32, 8);
    transpose_split_kernel<<<tgrid, tblk>>>(Wq, wqh, wql);
    transpose_split_kernel<<<tgrid, tblk>>>(Wk, wkh, wkl);
    transpose_split_kernel<<<tgrid, tblk>>>(Wv, wvh, wvl);
    transpose_split_kernel<<<tgrid, tblk>>>(Wo, woh, wol);

    // 2) QKV projections (warp MMA) -> bf16 hi/lo [B,H,S,HD]
    mma_gemm_kernel<0><<<dim3(GN / 128, GM / 128, 3), 256>>>(nullptr, nullptr);

    // 3) attention (warp MMA flash) -> ctx hi/lo [B,S,D]
    attn_mma_kernel<<<dim3(S_ / 64, B_ * H_), 128>>>();

    // 4) output projection + bias (warp MMA) -> fp32 out
    mma_gemm_kernel<1><<<dim3(GN / 128, GM / 128, 1), 256>>>(bo, out);
}

// round 6
// speedup vs baseline: 5.8250x; 1.1664x over previous
#include <cuda_runtime.h>
#include <cuda_bf16.h>
#include <cstdint>

// Problem dims
#define B_  2
#define S_  2048
#define D_  1024
#define H_  16
#define HD_ 64
#define GM  (B_ * S_)   // 4096
#define GN  D_          // 1024
#define GK  D_          // 1024

// ---------------------------------------------------------------------------
// Scratch (__device__ globals; allocation-free rule)
// ---------------------------------------------------------------------------
__device__ __nv_bfloat16 g_x_hi[GM * GK];
__device__ __nv_bfloat16 g_x_lo[GM * GK];
__device__ __nv_bfloat16 g_qh[B_ * H_ * S_ * HD_];   // [B,H,S,HD]
__device__ __nv_bfloat16 g_ql[B_ * H_ * S_ * HD_];
__device__ __nv_bfloat16 g_kh[B_ * H_ * S_ * HD_];
__device__ __nv_bfloat16 g_kl[B_ * H_ * S_ * HD_];
__device__ __nv_bfloat16 g_vh[B_ * H_ * S_ * HD_];
__device__ __nv_bfloat16 g_vl[B_ * H_ * S_ * HD_];
__device__ __nv_bfloat16 g_ctx_hi[GM * GK];          // [B,S,D]
__device__ __nv_bfloat16 g_ctx_lo[GM * GK];
// transposed weights [N, K] K-major
__device__ __nv_bfloat16 g_wqt_hi[GN * GK];
__device__ __nv_bfloat16 g_wqt_lo[GN * GK];
__device__ __nv_bfloat16 g_wkt_hi[GN * GK];
__device__ __nv_bfloat16 g_wkt_lo[GN * GK];
__device__ __nv_bfloat16 g_wvt_hi[GN * GK];
__device__ __nv_bfloat16 g_wvt_lo[GN * GK];
__device__ __nv_bfloat16 g_wot_hi[GN * GK];
__device__ __nv_bfloat16 g_wot_lo[GN * GK];

// ---------------------------------------------------------------------------
// Warp-MMA / async-copy primitives (sm_80+; valid for plain sm_103 target)
// ---------------------------------------------------------------------------
__device__ __forceinline__ uint32_t smem_u32(const void* p) {
    uint32_t a;
    asm("{ .reg .u64 t; cvta.to.shared.u64 t, %1; cvt.u32.u64 %0, t; }"
        : "=r"(a) : "l"(p));
    return a;
}

__device__ __forceinline__ void mma16816(float* c, const uint32_t* a,
                                         uint32_t b0, uint32_t b1) {
    asm volatile(
        "mma.sync.aligned.m16n8k16.row.col.f32.bf16.bf16.f32 "
        "{%0,%1,%2,%3}, {%4,%5,%6,%7}, {%8,%9}, {%0,%1,%2,%3};"
        : "+f"(c[0]), "+f"(c[1]), "+f"(c[2]), "+f"(c[3])
        : "r"(a[0]), "r"(a[1]), "r"(a[2]), "r"(a[3]), "r"(b0), "r"(b1));
}

__device__ __forceinline__ void ldmx4(uint32_t* r, uint32_t addr) {
    asm volatile("ldmatrix.sync.aligned.m8n8.x4.shared.b16 {%0,%1,%2,%3}, [%4];"
        : "=r"(r[0]), "=r"(r[1]), "=r"(r[2]), "=r"(r[3]) : "r"(addr));
}

__device__ __forceinline__ void ldmx4t(uint32_t* r, uint32_t addr) {
    asm volatile("ldmatrix.sync.aligned.m8n8.x4.trans.shared.b16 {%0,%1,%2,%3}, [%4];"
        : "=r"(r[0]), "=r"(r[1]), "=r"(r[2]), "=r"(r[3]) : "r"(addr));
}

__device__ __forceinline__ void cpa16(uint32_t s, const void* g) {
    asm volatile("cp.async.cg.shared.global [%0], [%1], 16;"
                 :: "r"(s), "l"(g) : "memory");
}
#define CP_COMMIT() asm volatile("cp.async.commit_group;" ::: "memory")
#define CP_WAIT(n)  asm volatile("cp.async.wait_group %0;" :: "n"(n) : "memory")

__device__ __forceinline__ unsigned pack_hi(float x, float y) {
    __nv_bfloat162 t = __floats2bfloat162_rn(x, y);
    return *reinterpret_cast<unsigned*>(&t);
}
__device__ __forceinline__ unsigned pack_lo(float x, float y) {
    float xr = x - __bfloat162float(__float2bfloat16(x));
    float yr = y - __bfloat162float(__float2bfloat16(y));
    __nv_bfloat162 t = __floats2bfloat162_rn(xr, yr);
    return *reinterpret_cast<unsigned*>(&t);
}

// ---------------------------------------------------------------------------
// GEMM: C[128,128] tile of A[M,K] @ B[N,K]^T, split-bf16 3-term, fp32 acc.
// 256 threads = 8 warps (2m x 4n); warp tile 64x32; KC=32; 2-stage cp.async.
// MODE 0: A = x, B = Wq/Wk/Wv (blockIdx.z); out -> bf16 hi/lo [B,H,S,HD]
// MODE 1: A = ctx, B = Wo; out -> fp32 [M,N] + bias
// ---------------------------------------------------------------------------
#define GP 40                 // smem pitch in bf16 (80 bytes)
#define GT (128 * GP * 2)     // one tile: 10240 bytes
#define GSTAGE (4 * GT)       // one stage (Ah,Al,Bh,Bl): 40960 bytes
#define SMEM_GEMM (2 * GSTAGE)

__device__ __forceinline__ void gemm_issue(uint32_t sb,
    const char* Ah, const char* Al, const char* Bh, const char* Bl,
    int m0, int n0, int c, int t)
{
    int lrow = t >> 1, lq = (t & 1) * 2;
    size_t goA = (size_t)(m0 + lrow) * (GK * 2) + (size_t)c * 64 + lq * 16;
    size_t goB = (size_t)(n0 + lrow) * (GK * 2) + (size_t)c * 64 + lq * 16;
    uint32_t soff = lrow * (GP * 2) + lq * 16;
    cpa16(sb + soff,               Ah + goA);
    cpa16(sb + soff + 16,          Ah + goA + 16);
    cpa16(sb + GT + soff,          Al + goA);
    cpa16(sb + GT + soff + 16,     Al + goA + 16);
    cpa16(sb + 2 * GT + soff,      Bh + goB);
    cpa16(sb + 2 * GT + soff + 16, Bh + goB + 16);
    cpa16(sb + 3 * GT + soff,      Bl + goB);
    cpa16(sb + 3 * GT + soff + 16, Bl + goB + 16);
}

template <int MODE>
__global__ __launch_bounds__(256, 1)
void mma_gemm_kernel(const float* __restrict__ bias, float* __restrict__ dout)
{
    extern __shared__ char smem[];
    const uint32_t sbase = smem_u32(smem);

    const __nv_bfloat16 *Ah, *Al, *Bh, *Bl;
    __nv_bfloat16 *OutH = nullptr, *OutL = nullptr;
    if (MODE == 0) {
        Ah = g_x_hi; Al = g_x_lo;
        if (blockIdx.z == 0)      { Bh = g_wqt_hi; Bl = g_wqt_lo; OutH = g_qh; OutL = g_ql; }
        else if (blockIdx.z == 1) { Bh = g_wkt_hi; Bl = g_wkt_lo; OutH = g_kh; OutL = g_kl; }
        else                      { Bh = g_wvt_hi; Bl = g_wvt_lo; OutH = g_vh; OutL = g_vl; }
    } else {
        Ah = g_ctx_hi; Al = g_ctx_lo; Bh = g_wot_hi; Bl = g_wot_lo;
    }

    const int m0   = blockIdx.y * 128;
    const int n0   = blockIdx.x * 128;
    const int t    = threadIdx.x;
    const int lane = t & 31;
    const int wid  = t >> 5;
    const int wm   = wid >> 2;     // 0..1
    const int wn   = wid & 3;      // 0..3

    float acc[4][4][4] = {};

    const int NC = GK / 32;
    gemm_issue(sbase, (const char*)Ah, (const char*)Al,
               (const char*)Bh, (const char*)Bl, m0, n0, 0, t);
    CP_COMMIT();

    for (int c = 0; c < NC; c++) {
        if (c + 1 < NC) {
            gemm_issue(sbase + ((c + 1) & 1) * GSTAGE,
                       (const char*)Ah, (const char*)Al,
                       (const char*)Bh, (const char*)Bl, m0, n0, c + 1, t);
            CP_COMMIT();
            CP_WAIT(1);
        } else {
            CP_WAIT(0);
        }
        __syncthreads();

        const uint32_t sb  = sbase + (c & 1) * GSTAGE;
        const uint32_t uAh = sb,          uAl = sb + GT;
        const uint32_t uBh = sb + 2 * GT, uBl = sb + 3 * GT;

        #pragma unroll
        for (int ks = 0; ks < 2; ks++) {
            uint32_t a_h[4][4], a_l[4][4];
            int abyte = (wm * 64 + (lane & 15)) * (GP * 2) + ks * 32 + (lane >> 4) * 16;
            #pragma unroll
            for (int mt = 0; mt < 4; mt++) {
                ldmx4(a_h[mt], uAh + abyte + mt * 16 * (GP * 2));
                ldmx4(a_l[mt], uAl + abyte + mt * 16 * (GP * 2));
            }
            #pragma unroll
            for (int j = 0; j < 2; j++) {
                uint32_t b_h[4], b_l[4];
                int bbyte = (wn * 32 + j * 16 + ((lane >> 4) << 3) + (lane & 7)) * (GP * 2)
                          + ks * 32 + ((lane >> 3) & 1) * 16;
                ldmx4(b_h, uBh + bbyte);
                ldmx4(b_l, uBl + bbyte);
                #pragma unroll
                for (int mt = 0; mt < 4; mt++) {
                    mma16816(acc[mt][2 * j],     a_h[mt], b_h[0], b_h[1]);
                    mma16816(acc[mt][2 * j],     a_h[mt], b_l[0], b_l[1]);
                    mma16816(acc[mt][2 * j],     a_l[mt], b_h[0], b_h[1]);
                    mma16816(acc[mt][2 * j + 1], a_h[mt], b_h[2], b_h[3]);
                    mma16816(acc[mt][2 * j + 1], a_h[mt], b_l[2], b_l[3]);
                    mma16816(acc[mt][2 * j + 1], a_l[mt], b_h[2], b_h[3]);
                }
            }
        }
        __syncthreads();
    }

    // Epilogue
    #pragma unroll
    for (int mt = 0; mt < 4; mt++) {
        int mA = m0 + wm * 64 + mt * 16 + (lane >> 2);
        int mB = mA + 8;
        #pragma unroll
        for (int nt = 0; nt < 4; nt++) {
            int n = n0 + wn * 32 + nt * 8 + (lane & 3) * 2;
            float c0 = acc[mt][nt][0], c1 = acc[mt][nt][1];
            float c2 = acc[mt][nt][2], c3 = acc[mt][nt][3];
            if (MODE == 0) {
                int h = n >> 6, hd = n & 63;
                {
                    int b = mA >> 11, s = mA & (S_ - 1);
                    size_t o = ((size_t)((b * H_ + h) * S_) + s) * HD_ + hd;
                    *(unsigned*)&OutH[o] = pack_hi(c0, c1);
                    *(unsigned*)&OutL[o] = pack_lo(c0, c1);
                }
                {
                    int b = mB >> 11, s = mB & (S_ - 1);
                    size_t o = ((size_t)((b * H_ + h) * S_) + s) * HD_ + hd;
                    *(unsigned*)&OutH[o] = pack_hi(c2, c3);
                    *(unsigned*)&OutL[o] = pack_lo(c2, c3);
                }
            } else {
                float b0 = bias[n], b1 = bias[n + 1];
                *(float2*)&dout[(size_t)mA * GN + n] = make_float2(c0 + b0, c1 + b1);
                *(float2*)&dout[(size_t)mB * GN + n] = make_float2(c2 + b0, c3 + b1);
            }
        }
    }
}

// ---------------------------------------------------------------------------
// Flash attention with warp MMA, causal, split-bf16 3-term, 2-stage cp.async.
// grid (S/64, B*H), 128 threads = 4 warps; warp owns 16 query rows.
// ---------------------------------------------------------------------------
#define AP 72                 // smem pitch in bf16 (144 bytes)
#define AT (64 * AP * 2)      // one tile: 9216 bytes
#define ASTAGE (4 * AT)       // Kh,Kl,Vh,Vl: 36864 bytes
#define SMEM_ATTN (2 * ASTAGE)

__device__ __forceinline__ void attn_issue_kv(uint32_t sb,
    const __nv_bfloat16* Kh, const __nv_bfloat16* Kl,
    const __nv_bfloat16* Vh, const __nv_bfloat16* Vl, int kb, int t)
{
    const uint4* gkh = (const uint4*)(Kh + (size_t)kb * 64 * HD_);
    const uint4* gkl = (const uint4*)(Kl + (size_t)kb * 64 * HD_);
    const uint4* gvh = (const uint4*)(Vh + (size_t)kb * 64 * HD_);
    const uint4* gvl = (const uint4*)(Vl + (size_t)kb * 64 * HD_);
    #pragma unroll
    for (int p = 0; p < 4; p++) {
        int idx = t + p * 128;
        int row = idx >> 3, q = idx & 7;
        uint32_t soff = row * (AP * 2) + q * 16;
        cpa16(sb + soff,          gkh + idx);
        cpa16(sb + AT + soff,     gkl + idx);
        cpa16(sb + 2 * AT + soff, gvh + idx);
        cpa16(sb + 3 * AT + soff, gvl + idx);
    }
}

__global__ __launch_bounds__(128, 2)
void attn_mma_kernel()
{
    extern __shared__ char smem[];
    const uint32_t sbase = smem_u32(smem);

    const int qb   = blockIdx.x;
    const int bh   = blockIdx.y;
    const int t    = threadIdx.x;
    const int lane = t & 31;
    const int wid  = t >> 5;

    const size_t head_off = (size_t)bh * S_ * HD_;
    const __nv_bfloat16* Qh = g_qh + head_off + (size_t)qb * 64 * HD_;
    const __nv_bfloat16* Ql = g_ql + head_off + (size_t)qb * 64 * HD_;
    const __nv_bfloat16* Kh = g_kh + head_off;
    const __nv_bfloat16* Kl = g_kl + head_off;
    const __nv_bfloat16* Vh = g_vh + head_off;
    const __nv_bfloat16* Vl = g_vl + head_off;

    // ---- stage Q into stage-1 K buffers via cp.async (group 0) ----
    {
        uint32_t qsb = sbase + ASTAGE;
        #pragma unroll
        for (int p = 0; p < 4; p++) {
            int idx = t + p * 128;
            int row = idx >> 3, q = idx & 7;
            uint32_t soff = row * (AP * 2) + q * 16;
            cpa16(qsb + soff,      ((const uint4*)Qh) + idx);
            cpa16(qsb + AT + soff, ((const uint4*)Ql) + idx);
        }
        CP_COMMIT();
    }
    // ---- kb=0 K/V into stage 0 (group 1) ----
    attn_issue_kv(sbase, Kh, Kl, Vh, Vl, 0, t);
    CP_COMMIT();

    CP_WAIT(1);           // Q group done; kb0 may still be in flight
    __syncthreads();

    uint32_t aq_h[4][4], aq_l[4][4];
    {
        uint32_t uQh = sbase + ASTAGE, uQl = sbase + ASTAGE + AT;
        int qbyte = (wid * 16 + (lane & 15)) * (AP * 2) + (lane >> 4) * 16;
        #pragma unroll
        for (int kc = 0; kc < 4; kc++) {
            ldmx4(aq_h[kc], uQh + qbyte + kc * 32);
            ldmx4(aq_l[kc], uQl + qbyte + kc * 32);
        }
    }
    __syncthreads();      // all warps have Q frags; stage-1 reusable

    float oAcc[8][4] = {};
    float m0r = -1e30f, m1r = -1e30f;
    float l0 = 0.0f, l1 = 0.0f;

    for (int kb = 0; kb <= qb; kb++) {
        if (kb < qb) {
            attn_issue_kv(sbase + ((kb + 1) & 1) * ASTAGE, Kh, Kl, Vh, Vl, kb + 1, t);
            CP_COMMIT();
            CP_WAIT(1);
        } else {
            CP_WAIT(0);
        }
        __syncthreads();

        const uint32_t sb  = sbase + (kb & 1) * ASTAGE;
        const uint32_t uKh = sb,          uKl = sb + AT;
        const uint32_t uVh = sb + 2 * AT, uVl = sb + 3 * AT;

        // ---- S = Q K^T (3-term) ----
        float sc[8][4] = {};
        #pragma unroll
        for (int kc = 0; kc < 4; kc++) {
            #pragma unroll
            for (int j = 0; j < 4; j++) {
                uint32_t b_h[4], b_l[4];
                int bbyte = (j * 16 + ((lane >> 4) << 3) + (lane & 7)) * (AP * 2)
                          + kc * 32 + ((lane >> 3) & 1) * 16;
                ldmx4(b_h, uKh + bbyte);
                ldmx4(b_l, uKl + bbyte);
                mma16816(sc[2 * j],     aq_h[kc], b_h[0], b_h[1]);
                mma16816(sc[2 * j],     aq_h[kc], b_l[0], b_l[1]);
                mma16816(sc[2 * j],     aq_l[kc], b_h[0], b_h[1]);
                mma16816(sc[2 * j + 1], aq_h[kc], b_h[2], b_h[3]);
                mma16816(sc[2 * j + 1], aq_h[kc], b_l[2], b_l[3]);
                mma16816(sc[2 * j + 1], aq_l[kc], b_h[2], b_h[3]);
            }
        }

        // ---- scale + causal mask (diagonal block only) ----
        #pragma unroll
        for (int nt = 0; nt < 8; nt++) {
            #pragma unroll
            for (int i = 0; i < 4; i++) sc[nt][i] *= 0.125f;
        }
        if (kb == qb) {
            int r0l = wid * 16 + (lane >> 2);
            #pragma unroll
            for (int nt = 0; nt < 8; nt++) {
                int col = nt * 8 + (lane & 3) * 2;
                if (col > r0l)         sc[nt][0] = -1e30f;
                if (col + 1 > r0l)     sc[nt][1] = -1e30f;
                if (col > r0l + 8)     sc[nt][2] = -1e30f;
                if (col + 1 > r0l + 8) sc[nt][3] = -1e30f;
            }
        }

        // ---- online softmax ----
        float mx0 = -1e30f, mx1 = -1e30f;
        #pragma unroll
        for (int nt = 0; nt < 8; nt++) {
            mx0 = fmaxf(mx0, fmaxf(sc[nt][0], sc[nt][1]));
            mx1 = fmaxf(mx1, fmaxf(sc[nt][2], sc[nt][3]));
        }
        mx0 = fmaxf(mx0, __shfl_xor_sync(0xffffffffu, mx0, 1));
        mx0 = fmaxf(mx0, __shfl_xor_sync(0xffffffffu, mx0, 2));
        mx1 = fmaxf(mx1, __shfl_xor_sync(0xffffffffu, mx1, 1));
        mx1 = fmaxf(mx1, __shfl_xor_sync(0xffffffffu, mx1, 2));

        float mn0 = fmaxf(m0r, mx0), mn1 = fmaxf(m1r, mx1);
        float cr0 = __expf(m0r - mn0), cr1 = __expf(m1r - mn1);

        float sum0 = 0.0f, sum1 = 0.0f;
        #pragma unroll
        for (int nt = 0; nt < 8; nt++) {
            float p0 = __expf(sc[nt][0] - mn0);
            float p1 = __expf(sc[nt][1] - mn0);
            float p2 = __expf(sc[nt][2] - mn1);
            float p3 = __expf(sc[nt][3] - mn1);
            sc[nt][0] = p0; sc[nt][1] = p1; sc[nt][2] = p2; sc[nt][3] = p3;
            sum0 += p0 + p1;
            sum1 += p2 + p3;
        }
        sum0 += __shfl_xor_sync(0xffffffffu, sum0, 1);
        sum0 += __shfl_xor_sync(0xffffffffu, sum0, 2);
        sum1 += __shfl_xor_sync(0xffffffffu, sum1, 1);
        sum1 += __shfl_xor_sync(0xffffffffu, sum1, 2);

        l0 = l0 * cr0 + sum0;  m0r = mn0;
        l1 = l1 * cr1 + sum1;  m1r = mn1;

        #pragma unroll
        for (int nt = 0; nt < 8; nt++) {
            oAcc[nt][0] *= cr0; oAcc[nt][1] *= cr0;
            oAcc[nt][2] *= cr1; oAcc[nt][3] *= cr1;
        }

        // ---- O += P V (3-term; V frags via ldmatrix.trans) ----
        #pragma unroll
        for (int kc = 0; kc < 4; kc++) {
            uint32_t pa_h[4], pa_l[4];
            pa_h[0] = pack_hi(sc[2 * kc][0],     sc[2 * kc][1]);
            pa_h[1] = pack_hi(sc[2 * kc][2],     sc[2 * kc][3]);
            pa_h[2] = pack_hi(sc[2 * kc + 1][0], sc[2 * kc + 1][1]);
            pa_h[3] = pack_hi(sc[2 * kc + 1][2], sc[2 * kc + 1][3]);
            pa_l[0] = pack_lo(sc[2 * kc][0],     sc[2 * kc][1]);
            pa_l[1] = pack_lo(sc[2 * kc][2],     sc[2 * kc][3]);
            pa_l[2] = pack_lo(sc[2 * kc + 1][0], sc[2 * kc + 1][1]);
            pa_l[3] = pack_lo(sc[2 * kc + 1][2], sc[2 * kc + 1][3]);
            #pragma unroll
            for (int j = 0; j < 4; j++) {
                uint32_t v_h[4], v_l[4];
                int key   = kc * 16 + ((lane >> 3) & 1) * 8 + (lane & 7);
                int hd    = j * 16 + (lane >> 4) * 8;
                int vbyte = key * (AP * 2) + hd * 2;
                ldmx4t(v_h, uVh + vbyte);
                ldmx4t(v_l, uVl + vbyte);
                mma16816(oAcc[2 * j],     pa_h, v_h[0], v_h[1]);
                mma16816(oAcc[2 * j],     pa_h, v_l[0], v_l[1]);
                mma16816(oAcc[2 * j],     pa_l, v_h[0], v_h[1]);
                mma16816(oAcc[2 * j + 1], pa_h, v_h[2], v_h[3]);
                mma16816(oAcc[2 * j + 1], pa_h, v_l[2], v_l[3]);
                mma16816(oAcc[2 * j + 1], pa_l, v_h[2], v_h[3]);
            }
        }
        __syncthreads();
    }

    // ---- finalize: ctx hi/lo bf16 [B,S,D] ----
    const float inv0 = 1.0f / l0, inv1 = 1.0f / l1;
    const int b = bh >> 4, h = bh & 15;
    const int r0 = qb * 64 + wid * 16 + (lane >> 2);
    const int r1 = r0 + 8;
    #pragma unroll
    for (int nt = 0; nt < 8; nt++) {
        int hd = nt * 8 + (lane & 3) * 2;
        float v0 = oAcc[nt][0] * inv0, v1 = oAcc[nt][1] * inv0;
        float v2 = oAcc[nt][2] * inv1, v3 = oAcc[nt][3] * inv1;
        size_t o0 = ((size_t)(b * S_ + r0)) * D_ + h * HD_ + hd;
        size_t o1 = ((size_t)(b * S_ + r1)) * D_ + h * HD_ + hd;
        *(unsigned*)&g_ctx_hi[o0] = pack_hi(v0, v1);
        *(unsigned*)&g_ctx_lo[o0] = pack_lo(v0, v1);
        *(unsigned*)&g_ctx_hi[o1] = pack_hi(v2, v3);
        *(unsigned*)&g_ctx_lo[o1] = pack_lo(v2, v3);
    }
}

// ---------------------------------------------------------------------------
// fp32 -> (bf16 hi, bf16 lo) split of x (writes device globals directly)
// ---------------------------------------------------------------------------
__global__ void split_x_kernel(const float4* __restrict__ src)
{
    int i = blockIdx.x * blockDim.x + threadIdx.x;
    if (i >= GM * GK / 4) return;
    float4 v = src[i];
    __nv_bfloat16 hx = __float2bfloat16(v.x), hy = __float2bfloat16(v.y);
    __nv_bfloat16 hz = __float2bfloat16(v.z), hw = __float2bfloat16(v.w);
    __nv_bfloat16 lx = __float2bfloat16(v.x - __bfloat162float(hx));
    __nv_bfloat16 ly = __float2bfloat16(v.y - __bfloat162float(hy));
    __nv_bfloat16 lz = __float2bfloat16(v.z - __bfloat162float(hz));
    __nv_bfloat16 lw = __float2bfloat16(v.w - __bfloat162float(hw));
    ((__nv_bfloat162*)g_x_hi)[i * 2]     = __nv_bfloat162(hx, hy);
    ((__nv_bfloat162*)g_x_hi)[i * 2 + 1] = __nv_bfloat162(hz, hw);
    ((__nv_bfloat162*)g_x_lo)[i * 2]     = __nv_bfloat162(lx, ly);
    ((__nv_bfloat162*)g_x_lo)[i * 2 + 1] = __nv_bfloat162(lz, lw);
}

// ---------------------------------------------------------------------------
// Batched: W [K,N] fp32 -> Wt [N,K] bf16 hi/lo for all 4 weights (blockIdx.z)
// ---------------------------------------------------------------------------
__global__ void transpose_split4_kernel(const float* __restrict__ W0,
                                        const float* __restrict__ W1,
                                        const float* __restrict__ W2,
                                        const float* __restrict__ W3)
{
    __shared__ float tile[32][33];
    const float* W;
    __nv_bfloat16 *hi, *lo;
    switch (blockIdx.z) {
        case 0:  W = W0; hi = g_wqt_hi; lo = g_wqt_lo; break;
        case 1:  W = W1; hi = g_wkt_hi; lo = g_wkt_lo; break;
        case 2:  W = W2; hi = g_wvt_hi; lo = g_wvt_lo; break;
        default: W = W3; hi = g_wot_hi; lo = g_wot_lo; break;
    }
    const int tx = threadIdx.x, ty = threadIdx.y;
    const int k0 = blockIdx.y * 32;
    const int n0 = blockIdx.x * 32;
    #pragma unroll
    for (int j = 0; j < 4; j++)
        tile[ty + j * 8][tx] = W[(size_t)(k0 + ty + j * 8) * GN + n0 + tx];
    __syncthreads();
    #pragma unroll
    for (int j = 0; j < 4; j++) {
        int n = n0 + ty + j * 8;
        int k = k0 + tx;
        float v = tile[tx][ty + j * 8];
        __nv_bfloat16 hv = __float2bfloat16(v);
        hi[(size_t)n * GK + k] = hv;
        lo[(size_t)n * GK + k] = __float2bfloat16(v - __bfloat162float(hv));
    }
}

// ---------------------------------------------------------------------------
extern "C" void kernel_launch(void* const* d_in, const int* in_sizes, int n_in,
                              void* d_out, int out_size)
{
    const float* x  = (const float*)d_in[0];
    const float* Wq = (const float*)d_in[1];
    const float* Wk = (const float*)d_in[2];
    const float* Wv = (const float*)d_in[3];
    const float* Wo = (const float*)d_in[4];
    const float* bo = (const float*)d_in[5];
    float*       out = (float*)d_out;

    cudaFuncSetAttribute(mma_gemm_kernel<0>,
                         cudaFuncAttributeMaxDynamicSharedMemorySize, SMEM_GEMM);
    cudaFuncSetAttribute(mma_gemm_kernel<1>,
                         cudaFuncAttributeMaxDynamicSharedMemorySize, SMEM_GEMM);
    cudaFuncSetAttribute(attn_mma_kernel,
                         cudaFuncAttributeMaxDynamicSharedMemorySize, SMEM_ATTN);

    // 1) prep: split x, transpose+split all 4 weights (batched)
    split_x_kernel<<<(GM * GK / 4 + 255) / 256, 256>>>((const float4*)x);
    transpose_split4_kernel<<<dim3(GN / 32, GK / 32, 4), dim3(32, 8)>>>(Wq, Wk, Wv, Wo);

    // 2) QKV projections (warp MMA, cp.async pipelined) -> bf16 hi/lo [B,H,S,HD]
    mma_gemm_kernel<0><<<dim3(GN / 128, GM / 128, 3), 256, SMEM_GEMM>>>(nullptr, nullptr);

    // 3) attention (warp MMA flash, cp.async pipelined) -> ctx hi/lo [B,S,D]
    attn_mma_kernel<<<dim3(S_ / 64, B_ * H_), 128, SMEM_ATTN>>>();

    // 4) output projection + bias (warp MMA) -> fp32 out
    mma_gemm_kernel<1><<<dim3(GN / 128, GM / 128, 1), 256, SMEM_GEMM>>>(bo, out);
}